// round 12
// baseline (speedup 1.0000x reference)
#include <cuda_runtime.h>
#include <cstdint>

// LinearBlendSkinning, R9: warp-autonomous tiles + VPT=2 + per-warp cp.async
// double buffering. out[n] = (sum_j w[n,j]*SE3[j])[:3,:3]@p[n] + T, N=1e6, J=55.
//
// R8 finding: stage->wait->compute serialized per warp; 28-float4 register
// staging batch pushed regs to 138 (occ 16.9%), and with ~11 warps/SM the LDG
// round-trip was exposed (nothing saturated). Fix: LDGSTS (cp.async.cg) writes
// SMEM directly (no registers), and each warp prefetches tile t+1 into its
// alternate buffer while computing tile t (commit_group/wait_group 1).
// Still zero block barriers: warps free-run and desynchronize.

#define NJ     55
#define WARPS  4
#define BT     (WARPS * 32)        // 128
#define TV     64                  // vertices per warp tile (VPT=2)
#define WSLICE (TV * NJ)           // 3520 floats = 14080 B per buffer
#define NQ     (WSLICE / 4)        // 880 float4
#define NCHUNK 28                  // ceil(880/32) cp.async per lane

#define FMA2(acc, s, m) \
    asm("fma.rn.f32x2 %0, %1, %2, %0;" : "+l"(acc) : "l"(s), "l"(m))
#define PACK_DUP(dst, f) \
    asm("mov.b64 %0, {%1, %1};" : "=l"(dst) : "f"(f))
#define UNPACK2(lo, hi, src) \
    asm("mov.b64 {%0, %1}, %2;" : "=f"(lo), "=f"(hi) : "l"(src))

#define CP16(dst_u32, src_ptr) \
    asm volatile("cp.async.cg.shared.global [%0], [%1], 16;" :: "r"(dst_u32), "l"(src_ptr))
#define CP4(dst_u32, src_ptr) \
    asm volatile("cp.async.ca.shared.global [%0], [%1], 4;"  :: "r"(dst_u32), "l"(src_ptr))
#define CP_COMMIT() asm volatile("cp.async.commit_group;" ::: "memory")
#define CP_WAIT(n)  asm volatile("cp.async.wait_group %0;" :: "n"(n) : "memory")

__device__ __forceinline__ uint32_t smem_u32(const void* p) {
    return (uint32_t)__cvta_generic_to_shared(p);
}

// dynamic SMEM: se3 rows (16B each) | [WARPS][2][WSLICE] weights
#define SMEM_BYTES (NJ * 3 * 16 + WARPS * 2 * WSLICE * 4)

__global__ void __launch_bounds__(BT, 2) lbs_kernel(
    const float* __restrict__ points,   // [N,3]
    const float* __restrict__ weights,  // [N,55]
    const float* __restrict__ se3g,     // [55,4,4]
    float* __restrict__ out,            // [N,3]
    int N, int ntiles)
{
    extern __shared__ unsigned char smem_raw[];
    ulonglong2* se3_s = (ulonglong2*)smem_raw;                  // [NJ*3]
    float*      w_all = (float*)(smem_raw + NJ * 3 * 16);       // [WARPS][2][WSLICE]

    const int tid  = threadIdx.x;
    const int wid  = tid >> 5;
    const int lane = tid & 31;

    // ---- SE3 rows 0..2 -> SMEM once per persistent block ----
    for (int idx = tid; idx < NJ * 3; idx += BT) {
        const int j = idx / 3, k = idx - j * 3;
        se3_s[idx] = *reinterpret_cast<const ulonglong2*>(se3g + j * 16 + k * 4);
    }
    __syncthreads();   // only block-wide sync in the kernel

    float* __restrict__ wbase = w_all + wid * 2 * WSLICE;
    const int tstride = gridDim.x * WARPS;
    const int t0 = blockIdx.x * WARPS + wid;

    // stage tile tt into buffer b (per-warp, async, no registers)
    auto stage = [&](int b, int tt) {
        const int vb = tt * TV;
        const int nv = min(TV, N - vb);
        const uint32_t dst = smem_u32(wbase + b * WSLICE);
        const float* __restrict__ src = weights + (size_t)vb * NJ;
        if (nv == TV) {
            #pragma unroll
            for (int k = 0; k < NCHUNK; k++) {
                const int i = lane + k * 32;
                if (i < NQ) CP16(dst + i * 16, src + i * 4);
            }
        } else {
            for (int i = lane; i < nv * NJ; i += 32) CP4(dst + i * 4, src + i);
        }
    };

    int buf = 0;
    if (t0 < ntiles) stage(0, t0);
    CP_COMMIT();

    for (int t = t0; t < ntiles; t += tstride) {
        const int base = t * TV;
        const int nv   = min(TV, N - base);

        const int v0 = base + lane;
        const int v1 = base + lane + 32;
        const bool valid0 = (lane      < nv);
        const bool valid1 = (lane + 32 < nv);
        const int pv0 = valid0 ? v0 : base;
        const int pv1 = valid1 ? v1 : base;

        // Points for tile t: independent of SMEM, issue before the wait.
        const float p0x = points[3 * pv0 + 0];
        const float p0y = points[3 * pv0 + 1];
        const float p0z = points[3 * pv0 + 2];
        const float p1x = points[3 * pv1 + 0];
        const float p1y = points[3 * pv1 + 1];
        const float p1z = points[3 * pv1 + 2];

        // Prefetch tile t+stride into the alternate buffer.
        const int  tn = t + tstride;
        const bool pf = (tn < ntiles);
        if (pf) stage(buf ^ 1, tn);
        CP_COMMIT();

        // Wait for tile t (allow the prefetch group to stay in flight).
        if (pf) { CP_WAIT(1); } else { CP_WAIT(0); }
        __syncwarp();

        // ---- compute both vertices; SE3 loads shared ----
        unsigned long long a000 = 0, a001 = 0, a010 = 0, a011 = 0, a020 = 0, a021 = 0;
        unsigned long long a100 = 0, a101 = 0, a110 = 0, a111 = 0, a120 = 0, a121 = 0;
        const float* __restrict__ ws  = wbase + buf * WSLICE;
        const float* __restrict__ wp0 = ws + lane * NJ;          // stride 55: cf-free
        const float* __restrict__ wp1 = ws + (lane + 32) * NJ;

        #pragma unroll 11
        for (int j = 0; j < NJ; j++) {
            const float w0 = wp0[j];
            const float w1 = wp1[j];
            unsigned long long ww0, ww1;
            PACK_DUP(ww0, w0);
            PACK_DUP(ww1, w1);
            const ulonglong2 r0 = se3_s[j * 3 + 0];      // LDS.128 broadcast
            const ulonglong2 r1 = se3_s[j * 3 + 1];
            const ulonglong2 r2 = se3_s[j * 3 + 2];
            FMA2(a000, ww0, r0.x); FMA2(a001, ww0, r0.y);
            FMA2(a010, ww0, r1.x); FMA2(a011, ww0, r1.y);
            FMA2(a020, ww0, r2.x); FMA2(a021, ww0, r2.y);
            FMA2(a100, ww1, r0.x); FMA2(a101, ww1, r0.y);
            FMA2(a110, ww1, r1.x); FMA2(a111, ww1, r1.y);
            FMA2(a120, ww1, r2.x); FMA2(a121, ww1, r2.y);
        }

        float m0, m1, m2, m3;
        if (valid0) {
            float o0, o1, o2;
            UNPACK2(m0, m1, a000); UNPACK2(m2, m3, a001);
            o0 = fmaf(m0, p0x, fmaf(m1, p0y, fmaf(m2, p0z, m3)));
            UNPACK2(m0, m1, a010); UNPACK2(m2, m3, a011);
            o1 = fmaf(m0, p0x, fmaf(m1, p0y, fmaf(m2, p0z, m3)));
            UNPACK2(m0, m1, a020); UNPACK2(m2, m3, a021);
            o2 = fmaf(m0, p0x, fmaf(m1, p0y, fmaf(m2, p0z, m3)));
            out[3 * v0 + 0] = o0;
            out[3 * v0 + 1] = o1;
            out[3 * v0 + 2] = o2;
        }
        if (valid1) {
            float o0, o1, o2;
            UNPACK2(m0, m1, a100); UNPACK2(m2, m3, a101);
            o0 = fmaf(m0, p1x, fmaf(m1, p1y, fmaf(m2, p1z, m3)));
            UNPACK2(m0, m1, a110); UNPACK2(m2, m3, a111);
            o1 = fmaf(m0, p1x, fmaf(m1, p1y, fmaf(m2, p1z, m3)));
            UNPACK2(m0, m1, a120); UNPACK2(m2, m3, a121);
            o2 = fmaf(m0, p1x, fmaf(m1, p1y, fmaf(m2, p1z, m3)));
            out[3 * v1 + 0] = o0;
            out[3 * v1 + 1] = o1;
            out[3 * v1 + 2] = o2;
        }

        buf ^= 1;
    }
}

extern "C" void kernel_launch(void* const* d_in, const int* in_sizes, int n_in,
                              void* d_out, int out_size)
{
    const float* points  = (const float*)d_in[0];  // [N,3]
    const float* weights = (const float*)d_in[1];  // [N,55]
    const float* se3     = (const float*)d_in[2];  // [55,4,4]
    float* out           = (float*)d_out;          // [N,3]

    const int N      = in_sizes[0] / 3;
    const int ntiles = (N + TV - 1) / TV;

    int grid = 148 * 2;                        // persistent: 2 blocks/SM
    const int maxg = (ntiles + WARPS - 1) / WARPS;
    if (grid > maxg) grid = maxg;

    static bool attr_set = false;
    if (!attr_set) {
        cudaFuncSetAttribute(lbs_kernel,
                             cudaFuncAttributeMaxDynamicSharedMemorySize,
                             SMEM_BYTES);
        attr_set = true;
    }
    lbs_kernel<<<grid, BT, SMEM_BYTES>>>(points, weights, se3, out, N, ntiles);
}